// round 9
// baseline (speedup 1.0000x reference)
#include <cuda_runtime.h>
#include <cstdint>

#define NLAYER 16
#define BATCH 8
#define TLEN 65536
#define NTOT (BATCH*TLEN)        // 524288
#define RES 32
#define KTOT (NLAYER*RES)        // 512

// per-layer coefficient layout (floats), stride 420
#define C_AF0 0
#define C_AF1 32
#define C_AF2 64
#define C_BFA 96
#define C_DF0 128
#define C_DF1 160
#define C_AG0 192
#define C_AG1 224
#define C_AG2 256
#define C_BGA 288
#define C_DG0 320
#define C_DG1 352
#define C_WO  384
#define C_BO  416
#define C_STRIDE 420

__device__ float g_coef[NLAYER*C_STRIDE];
__device__ float g_G[KTOT*64];      // folded (W_sk1 @ W_s_cat), layout [j][m]
__device__ float g_C1[64];          // folded bias into pre-relu
__device__ float g_bufA[NTOT];
__device__ float g_bufB[NTOT];
__device__ float g_gated[(size_t)KTOT*NTOT];   // 1 GiB scratch, layout [j][n]

// ---------------------------------------------------------------------------
// Precompute 1: collapse the per-layer convs onto the scalar residual stream.
// residual = W_in*out + b_in (1 input channel) =>
// f_pre(t,c) = sum_k mask_k*(A_f[k,c]*out(t-(2-k)d) + D_f[k,c]) + b_f[c]
// ---------------------------------------------------------------------------
__global__ void precompute_layer(const float* __restrict__ W_in, const float* __restrict__ b_in,
                                 const float* __restrict__ W_f,  const float* __restrict__ b_f,
                                 const float* __restrict__ W_g,  const float* __restrict__ b_g,
                                 const float* __restrict__ W_o,  const float* __restrict__ b_o)
{
    int i = blockIdx.x;      // layer
    int c = threadIdx.x;     // out channel (32)
    float af[3] = {0,0,0}, df[3] = {0,0,0};
    float ag[3] = {0,0,0}, dg[3] = {0,0,0};
    for (int cin = 0; cin < 32; cin++) {
        float wi = W_in[i*32 + cin];
        float bi = b_in[i*32 + cin];
        #pragma unroll
        for (int k = 0; k < 3; k++) {
            float wf = W_f[((i*32 + c)*32 + cin)*3 + k];
            float wg = W_g[((i*32 + c)*32 + cin)*3 + k];
            af[k] = fmaf(wf, wi, af[k]);
            df[k] = fmaf(wf, bi, df[k]);
            ag[k] = fmaf(wg, wi, ag[k]);
            dg[k] = fmaf(wg, bi, dg[k]);
        }
    }
    float* cf = g_coef + i*C_STRIDE;
    cf[C_AF0+c] = af[0]; cf[C_AF1+c] = af[1]; cf[C_AF2+c] = af[2];
    cf[C_BFA+c] = b_f[i*32 + c] + df[0] + df[1] + df[2];  // fast path: all taps valid
    cf[C_DF0+c] = df[0]; cf[C_DF1+c] = df[1];
    cf[C_AG0+c] = ag[0]; cf[C_AG1+c] = ag[1]; cf[C_AG2+c] = ag[2];
    cf[C_BGA+c] = b_g[i*32 + c] + dg[0] + dg[1] + dg[2];
    cf[C_DG0+c] = dg[0]; cf[C_DG1+c] = dg[1];
    cf[C_WO +c] = W_o[i*32 + c];
    if (c == 0) cf[C_BO] = b_o[i];
}

// ---------------------------------------------------------------------------
// Precompute 2: fold skip path.  pre_relu = (W_sk1 @ W_s_cat) @ gated + c1
// ---------------------------------------------------------------------------
__global__ void precompute_skip(const float* __restrict__ W_s,   const float* __restrict__ b_s,
                                const float* __restrict__ W_sk1, const float* __restrict__ b_sk1)
{
    int gid = blockIdx.x*blockDim.x + threadIdx.x;
    if (gid < KTOT*64) {
        int j = gid >> 6, m = gid & 63;
        int i = j >> 5, c = j & 31;
        float acc = 0.f;
        for (int o = 0; o < 64; o++)
            acc = fmaf(W_sk1[m*64 + o], W_s[(i*64 + o)*32 + c], acc);
        g_G[j*64 + m] = acc;
    }
    if (gid < 64) {
        int m = gid;
        float acc = b_sk1[m];
        for (int o = 0; o < 64; o++) {
            float bs = 0.f;
            for (int i2 = 0; i2 < NLAYER; i2++) bs += b_s[i2*64 + o];
            acc = fmaf(W_sk1[m*64 + o], bs, acc);
        }
        g_C1[m] = acc;
    }
}

// ---------------------------------------------------------------------------
// Phase A: one kernel per layer on the collapsed form.
// ---------------------------------------------------------------------------
__device__ __forceinline__ float fast_tanh(float x) {
    float e = __expf(2.f*x);
    return 1.f - __fdividef(2.f, e + 1.f);
}
__device__ __forceinline__ float fast_sigmoid(float x) {
    return __fdividef(1.f, 1.f + __expf(-x));
}

#define AU 4
__global__ void __launch_bounds__(256) layer_kernel(const float* __restrict__ x, int layer, int d)
{
    __shared__ float cf[C_STRIDE];
    {
        const float* gc = g_coef + layer*C_STRIDE;
        for (int idx = threadIdx.x; idx < C_STRIDE; idx += 256) cf[idx] = gc[idx];
    }
    __syncthreads();

    const float* in = (layer == 0) ? x : ((layer & 1) ? g_bufA : g_bufB);
    float* out = (layer & 1) ? g_bufB : g_bufA;
    float* gp = g_gated + (size_t)layer*RES*NTOT;

    int base = blockIdx.x*(256*AU) + threadIdx.x;

    float o0[AU], o1[AU], o2[AU], acc[AU];
    int tt[AU];
    #pragma unroll
    for (int u = 0; u < AU; u++) {
        int n = base + u*256;
        int t = n & (TLEN - 1);
        tt[u] = t;
        o2[u] = in[n];
        o1[u] = (t >= d)   ? in[n - d]   : 0.f;
        o0[u] = (t >= 2*d) ? in[n - 2*d] : 0.f;
        acc[u] = 0.f;
    }
    float bo = cf[C_BO];

    #pragma unroll 4
    for (int c = 0; c < RES; c++) {
        float af0 = cf[C_AF0+c], af1 = cf[C_AF1+c], af2 = cf[C_AF2+c], bfa = cf[C_BFA+c];
        float ag0 = cf[C_AG0+c], ag1 = cf[C_AG1+c], ag2 = cf[C_AG2+c], bga = cf[C_BGA+c];
        float wo  = cf[C_WO+c];
        float* gout = gp + (size_t)c*NTOT;
        #pragma unroll
        for (int u = 0; u < AU; u++) {
            float pf = fmaf(af0, o0[u], fmaf(af1, o1[u], fmaf(af2, o2[u], bfa)));
            float pg = fmaf(ag0, o0[u], fmaf(ag1, o1[u], fmaf(ag2, o2[u], bga)));
            if (tt[u] < 2*d) {   // rare: remove bias contributions of zero-padded taps
                pf -= cf[C_DF0+c]; pg -= cf[C_DG0+c];
                if (tt[u] < d) { pf -= cf[C_DF1+c]; pg -= cf[C_DG1+c]; }
            }
            float f = fast_tanh(pf);
            float g = fast_sigmoid(pg);
            float gt = f*g;
            gout[base + u*256] = gt;           // coalesced per-c row store
            acc[u] = fmaf(wo, gt, acc[u]);
        }
    }
    #pragma unroll
    for (int u = 0; u < AU; u++) {
        int n = base + u*256;
        out[n] = o2[u] + acc[u] + bo;
    }
}

// ---------------------------------------------------------------------------
// Phase B: pre[64,N] = G[64,512] @ gated[512,N] + c1, relu, 2-ch head, exp.
// Uses packed fma.rn.f32x2 (2 samples per FMA) — 2x FFMA rate on sm_103a.
// Tile: 128 samples x 64 outputs per block; thread = 4 outputs x 8 samples.
// ---------------------------------------------------------------------------
#define NT 128
#define KC 16
__global__ void __launch_bounds__(256) phaseB_kernel(const float* __restrict__ W_sk2,
                                                     const float* __restrict__ b_sk2,
                                                     float* __restrict__ outp)
{
    __shared__ __align__(16) float2 sG2[KC][64];     // duplicated G for f32x2 broadcast
    __shared__ __align__(16) float  sX[KC][NT];
    __shared__ float sRed[16][2][132];

    int tid  = threadIdx.x;
    int n0   = blockIdx.x * NT;
    int mgrp = tid >> 4;   // 0..15  -> outputs mgrp*4 .. +3
    int pgrp = tid & 15;   // 0..15  -> samples pgrp*8 .. +7

    unsigned long long acc[4][4];
    #pragma unroll
    for (int a = 0; a < 4; a++)
        #pragma unroll
        for (int b = 0; b < 4; b++) acc[a][b] = 0ULL;

    for (int jb = 0; jb < KTOT; jb += KC) {
        {   // stage G (dup each scalar into both f32x2 lanes)
            int kk = tid >> 4, m4 = tid & 15;
            float4 gv = *reinterpret_cast<const float4*>(&g_G[(jb + kk)*64 + m4*4]);
            sG2[kk][m4*4+0] = make_float2(gv.x, gv.x);
            sG2[kk][m4*4+1] = make_float2(gv.y, gv.y);
            sG2[kk][m4*4+2] = make_float2(gv.z, gv.z);
            sG2[kk][m4*4+3] = make_float2(gv.w, gv.w);
        }
        #pragma unroll
        for (int q = 0; q < 2; q++) {   // stage gated tile
            int fid = tid + q*256;
            int kk = fid >> 5, s4 = fid & 31;
            *reinterpret_cast<float4*>(&sX[kk][s4*4]) =
                *reinterpret_cast<const float4*>(&g_gated[(size_t)(jb + kk)*NTOT + n0 + s4*4]);
        }
        __syncthreads();
        #pragma unroll
        for (int kk = 0; kk < KC; kk++) {
            ulonglong2 xa = *reinterpret_cast<const ulonglong2*>(&sX[kk][pgrp*8]);
            ulonglong2 xb = *reinterpret_cast<const ulonglong2*>(&sX[kk][pgrp*8 + 4]);
            unsigned long long xp[4] = {xa.x, xa.y, xb.x, xb.y};
            #pragma unroll
            for (int mm = 0; mm < 4; mm++) {
                unsigned long long gg =
                    *reinterpret_cast<const unsigned long long*>(&sG2[kk][mgrp*4 + mm]);
                #pragma unroll
                for (int q = 0; q < 4; q++) {
                    asm("fma.rn.f32x2 %0, %1, %2, %0;"
                        : "+l"(acc[mm][q]) : "l"(gg), "l"(xp[q]));
                }
            }
        }
        __syncthreads();
    }

    // epilogue: +c1, relu, project to 2 channels (partial over this thread's 4 m)
    float p0[8], p1[8];
    #pragma unroll
    for (int s = 0; s < 8; s++) { p0[s] = 0.f; p1[s] = 0.f; }
    #pragma unroll
    for (int mm = 0; mm < 4; mm++) {
        int m = mgrp*4 + mm;
        float c1v = g_C1[m];
        float w0 = W_sk2[m];       // channel 0 row
        float w1 = W_sk2[64 + m];  // channel 1 row
        #pragma unroll
        for (int q = 0; q < 4; q++) {
            unsigned lo32, hi32;
            asm("mov.b64 {%0,%1}, %2;" : "=r"(lo32), "=r"(hi32) : "l"(acc[mm][q]));
            float vlo = fmaxf(__uint_as_float(lo32) + c1v, 0.f);
            float vhi = fmaxf(__uint_as_float(hi32) + c1v, 0.f);
            p0[2*q]   = fmaf(w0, vlo, p0[2*q]);
            p0[2*q+1] = fmaf(w0, vhi, p0[2*q+1]);
            p1[2*q]   = fmaf(w1, vlo, p1[2*q]);
            p1[2*q+1] = fmaf(w1, vhi, p1[2*q+1]);
        }
    }
    #pragma unroll
    for (int s = 0; s < 8; s++) {
        sRed[mgrp][0][pgrp*8 + s] = p0[s];
        sRed[mgrp][1][pgrp*8 + s] = p1[s];
    }
    __syncthreads();
    {   // cross-mgrp reduction: thread -> one (channel, sample)
        int ch = tid >> 7, s = tid & 127;
        float sum = 0.f;
        #pragma unroll
        for (int mg = 0; mg < 16; mg++) sum += sRed[mg][ch][s];
        sum += b_sk2[ch];
        int n = n0 + s;
        if (ch == 0) outp[n] = sum;                       // means
        else         outp[NTOT + n] = __expf(0.5f*sum);   // stds
    }
}

// ---------------------------------------------------------------------------
extern "C" void kernel_launch(void* const* d_in, const int* in_sizes, int n_in,
                              void* d_out, int out_size)
{
    const float* x     = (const float*)d_in[0];
    const float* W_in  = (const float*)d_in[1];
    const float* b_in  = (const float*)d_in[2];
    const float* W_f   = (const float*)d_in[3];
    const float* b_f   = (const float*)d_in[4];
    const float* W_g   = (const float*)d_in[5];
    const float* b_g   = (const float*)d_in[6];
    const float* W_s   = (const float*)d_in[7];
    const float* b_s   = (const float*)d_in[8];
    const float* W_o   = (const float*)d_in[9];
    const float* b_o   = (const float*)d_in[10];
    const float* W_sk1 = (const float*)d_in[11];
    const float* b_sk1 = (const float*)d_in[12];
    const float* W_sk2 = (const float*)d_in[13];
    const float* b_sk2 = (const float*)d_in[14];
    float* outp = (float*)d_out;

    precompute_layer<<<NLAYER, 32>>>(W_in, b_in, W_f, b_f, W_g, b_g, W_o, b_o);
    precompute_skip<<<128, 256>>>(W_s, b_s, W_sk1, b_sk1);

    for (int i = 0; i < NLAYER; i++) {
        int d = 1 << (i & 7);
        layer_kernel<<<NTOT/(256*AU), 256>>>(x, i, d);
    }
    phaseB_kernel<<<NTOT/NT, 256>>>(W_sk2, b_sk2, outp);
}

// round 10
// speedup vs baseline: 1.0032x; 1.0032x over previous
#include <cuda_runtime.h>
#include <cstdint>

#define NLAYER 16
#define BATCH 8
#define TLEN 65536
#define NTOT (BATCH*TLEN)        // 524288
#define RES 32
#define KTOT (NLAYER*RES)        // 512

// per-layer coefficient layout (floats), stride 420
#define C_AF0 0
#define C_AF1 32
#define C_AF2 64
#define C_BFA 96
#define C_DF0 128
#define C_DF1 160
#define C_AG0 192
#define C_AG1 224
#define C_AG2 256
#define C_BGA 288
#define C_DG0 320
#define C_DG1 352
#define C_WO  384
#define C_BO  416
#define C_STRIDE 420

__device__ float g_coef[NLAYER*C_STRIDE];
__device__ float g_G[KTOT*64];      // folded (W_sk1 @ W_s_cat), layout [j][m]
__device__ float g_C1[64];          // folded bias into pre-relu
__device__ float g_bufA[NTOT];
__device__ float g_bufB[NTOT];
__device__ float g_gated[(size_t)KTOT*NTOT];   // 1 GiB scratch, layout [j][n]

// ---------------------------------------------------------------------------
// Precompute 1: collapse the per-layer convs onto the scalar residual stream.
// residual = W_in*out + b_in (1 input channel) =>
// f_pre(t,c) = sum_k mask_k*(A_f[k,c]*out(t-(2-k)d) + D_f[k,c]) + b_f[c]
// ---------------------------------------------------------------------------
__global__ void precompute_layer(const float* __restrict__ W_in, const float* __restrict__ b_in,
                                 const float* __restrict__ W_f,  const float* __restrict__ b_f,
                                 const float* __restrict__ W_g,  const float* __restrict__ b_g,
                                 const float* __restrict__ W_o,  const float* __restrict__ b_o)
{
    int i = blockIdx.x;      // layer
    int c = threadIdx.x;     // out channel (32)
    float af[3] = {0,0,0}, df[3] = {0,0,0};
    float ag[3] = {0,0,0}, dg[3] = {0,0,0};
    for (int cin = 0; cin < 32; cin++) {
        float wi = W_in[i*32 + cin];
        float bi = b_in[i*32 + cin];
        #pragma unroll
        for (int k = 0; k < 3; k++) {
            float wf = W_f[((i*32 + c)*32 + cin)*3 + k];
            float wg = W_g[((i*32 + c)*32 + cin)*3 + k];
            af[k] = fmaf(wf, wi, af[k]);
            df[k] = fmaf(wf, bi, df[k]);
            ag[k] = fmaf(wg, wi, ag[k]);
            dg[k] = fmaf(wg, bi, dg[k]);
        }
    }
    float* cf = g_coef + i*C_STRIDE;
    cf[C_AF0+c] = af[0]; cf[C_AF1+c] = af[1]; cf[C_AF2+c] = af[2];
    cf[C_BFA+c] = b_f[i*32 + c] + df[0] + df[1] + df[2];  // fast path: all taps valid
    cf[C_DF0+c] = df[0]; cf[C_DF1+c] = df[1];
    cf[C_AG0+c] = ag[0]; cf[C_AG1+c] = ag[1]; cf[C_AG2+c] = ag[2];
    cf[C_BGA+c] = b_g[i*32 + c] + dg[0] + dg[1] + dg[2];
    cf[C_DG0+c] = dg[0]; cf[C_DG1+c] = dg[1];
    cf[C_WO +c] = W_o[i*32 + c];
    if (c == 0) cf[C_BO] = b_o[i];
}

// ---------------------------------------------------------------------------
// Precompute 2: fold skip path.  pre_relu = (W_sk1 @ W_s_cat) @ gated + c1
// ---------------------------------------------------------------------------
__global__ void precompute_skip(const float* __restrict__ W_s,   const float* __restrict__ b_s,
                                const float* __restrict__ W_sk1, const float* __restrict__ b_sk1)
{
    int gid = blockIdx.x*blockDim.x + threadIdx.x;
    if (gid < KTOT*64) {
        int j = gid >> 6, m = gid & 63;
        int i = j >> 5, c = j & 31;
        float acc = 0.f;
        for (int o = 0; o < 64; o++)
            acc = fmaf(W_sk1[m*64 + o], W_s[(i*64 + o)*32 + c], acc);
        g_G[j*64 + m] = acc;
    }
    if (gid < 64) {
        int m = gid;
        float acc = b_sk1[m];
        for (int o = 0; o < 64; o++) {
            float bs = 0.f;
            for (int i2 = 0; i2 < NLAYER; i2++) bs += b_s[i2*64 + o];
            acc = fmaf(W_sk1[m*64 + o], bs, acc);
        }
        g_C1[m] = acc;
    }
}

// ---------------------------------------------------------------------------
// Phase A: one kernel per layer on the collapsed form.
// ---------------------------------------------------------------------------
__device__ __forceinline__ float fast_tanh(float x) {
    float e = __expf(2.f*x);
    return 1.f - __fdividef(2.f, e + 1.f);
}
__device__ __forceinline__ float fast_sigmoid(float x) {
    return __fdividef(1.f, 1.f + __expf(-x));
}

#define AU 4
__global__ void __launch_bounds__(256) layer_kernel(const float* __restrict__ x, int layer, int d)
{
    __shared__ float cf[C_STRIDE];
    {
        const float* gc = g_coef + layer*C_STRIDE;
        for (int idx = threadIdx.x; idx < C_STRIDE; idx += 256) cf[idx] = gc[idx];
    }
    __syncthreads();

    const float* in = (layer == 0) ? x : ((layer & 1) ? g_bufA : g_bufB);
    float* out = (layer & 1) ? g_bufB : g_bufA;
    float* gp = g_gated + (size_t)layer*RES*NTOT;

    int base = blockIdx.x*(256*AU) + threadIdx.x;

    float o0[AU], o1[AU], o2[AU], acc[AU];
    int tt[AU];
    #pragma unroll
    for (int u = 0; u < AU; u++) {
        int n = base + u*256;
        int t = n & (TLEN - 1);
        tt[u] = t;
        o2[u] = in[n];
        o1[u] = (t >= d)   ? in[n - d]   : 0.f;
        o0[u] = (t >= 2*d) ? in[n - 2*d] : 0.f;
        acc[u] = 0.f;
    }
    float bo = cf[C_BO];

    #pragma unroll 4
    for (int c = 0; c < RES; c++) {
        float af0 = cf[C_AF0+c], af1 = cf[C_AF1+c], af2 = cf[C_AF2+c], bfa = cf[C_BFA+c];
        float ag0 = cf[C_AG0+c], ag1 = cf[C_AG1+c], ag2 = cf[C_AG2+c], bga = cf[C_BGA+c];
        float wo  = cf[C_WO+c];
        float* gout = gp + (size_t)c*NTOT;
        #pragma unroll
        for (int u = 0; u < AU; u++) {
            float pf = fmaf(af0, o0[u], fmaf(af1, o1[u], fmaf(af2, o2[u], bfa)));
            float pg = fmaf(ag0, o0[u], fmaf(ag1, o1[u], fmaf(ag2, o2[u], bga)));
            if (tt[u] < 2*d) {   // rare: remove bias contributions of zero-padded taps
                pf -= cf[C_DF0+c]; pg -= cf[C_DG0+c];
                if (tt[u] < d) { pf -= cf[C_DF1+c]; pg -= cf[C_DG1+c]; }
            }
            float f = fast_tanh(pf);
            float g = fast_sigmoid(pg);
            float gt = f*g;
            gout[base + u*256] = gt;           // coalesced per-c row store
            acc[u] = fmaf(wo, gt, acc[u]);
        }
    }
    #pragma unroll
    for (int u = 0; u < AU; u++) {
        int n = base + u*256;
        out[n] = o2[u] + acc[u] + bo;
    }
}

// ---------------------------------------------------------------------------
// Phase B: pre[64,N] = G[64,512] @ gated[512,N] + c1, relu, 2-ch head, exp.
// Uses packed fma.rn.f32x2 (2 samples per FMA) — 2x FFMA rate on sm_103a.
// Tile: 128 samples x 64 outputs per block; thread = 4 outputs x 8 samples.
// ---------------------------------------------------------------------------
#define NT 128
#define KC 16
__global__ void __launch_bounds__(256) phaseB_kernel(const float* __restrict__ W_sk2,
                                                     const float* __restrict__ b_sk2,
                                                     float* __restrict__ outp)
{
    __shared__ __align__(16) float2 sG2[KC][64];     // duplicated G for f32x2 broadcast
    __shared__ __align__(16) float  sX[KC][NT];
    __shared__ float sRed[16][2][132];

    int tid  = threadIdx.x;
    int n0   = blockIdx.x * NT;
    int mgrp = tid >> 4;   // 0..15  -> outputs mgrp*4 .. +3
    int pgrp = tid & 15;   // 0..15  -> samples pgrp*8 .. +7

    unsigned long long acc[4][4];
    #pragma unroll
    for (int a = 0; a < 4; a++)
        #pragma unroll
        for (int b = 0; b < 4; b++) acc[a][b] = 0ULL;

    for (int jb = 0; jb < KTOT; jb += KC) {
        {   // stage G (dup each scalar into both f32x2 lanes)
            int kk = tid >> 4, m4 = tid & 15;
            float4 gv = *reinterpret_cast<const float4*>(&g_G[(jb + kk)*64 + m4*4]);
            sG2[kk][m4*4+0] = make_float2(gv.x, gv.x);
            sG2[kk][m4*4+1] = make_float2(gv.y, gv.y);
            sG2[kk][m4*4+2] = make_float2(gv.z, gv.z);
            sG2[kk][m4*4+3] = make_float2(gv.w, gv.w);
        }
        #pragma unroll
        for (int q = 0; q < 2; q++) {   // stage gated tile
            int fid = tid + q*256;
            int kk = fid >> 5, s4 = fid & 31;
            *reinterpret_cast<float4*>(&sX[kk][s4*4]) =
                *reinterpret_cast<const float4*>(&g_gated[(size_t)(jb + kk)*NTOT + n0 + s4*4]);
        }
        __syncthreads();
        #pragma unroll
        for (int kk = 0; kk < KC; kk++) {
            ulonglong2 xa = *reinterpret_cast<const ulonglong2*>(&sX[kk][pgrp*8]);
            ulonglong2 xb = *reinterpret_cast<const ulonglong2*>(&sX[kk][pgrp*8 + 4]);
            unsigned long long xp[4] = {xa.x, xa.y, xb.x, xb.y};
            #pragma unroll
            for (int mm = 0; mm < 4; mm++) {
                unsigned long long gg =
                    *reinterpret_cast<const unsigned long long*>(&sG2[kk][mgrp*4 + mm]);
                #pragma unroll
                for (int q = 0; q < 4; q++) {
                    asm("fma.rn.f32x2 %0, %1, %2, %0;"
                        : "+l"(acc[mm][q]) : "l"(gg), "l"(xp[q]));
                }
            }
        }
        __syncthreads();
    }

    // epilogue: +c1, relu, project to 2 channels (partial over this thread's 4 m)
    float p0[8], p1[8];
    #pragma unroll
    for (int s = 0; s < 8; s++) { p0[s] = 0.f; p1[s] = 0.f; }
    #pragma unroll
    for (int mm = 0; mm < 4; mm++) {
        int m = mgrp*4 + mm;
        float c1v = g_C1[m];
        float w0 = W_sk2[m];       // channel 0 row
        float w1 = W_sk2[64 + m];  // channel 1 row
        #pragma unroll
        for (int q = 0; q < 4; q++) {
            unsigned lo32, hi32;
            asm("mov.b64 {%0,%1}, %2;" : "=r"(lo32), "=r"(hi32) : "l"(acc[mm][q]));
            float vlo = fmaxf(__uint_as_float(lo32) + c1v, 0.f);
            float vhi = fmaxf(__uint_as_float(hi32) + c1v, 0.f);
            p0[2*q]   = fmaf(w0, vlo, p0[2*q]);
            p0[2*q+1] = fmaf(w0, vhi, p0[2*q+1]);
            p1[2*q]   = fmaf(w1, vlo, p1[2*q]);
            p1[2*q+1] = fmaf(w1, vhi, p1[2*q+1]);
        }
    }
    #pragma unroll
    for (int s = 0; s < 8; s++) {
        sRed[mgrp][0][pgrp*8 + s] = p0[s];
        sRed[mgrp][1][pgrp*8 + s] = p1[s];
    }
    __syncthreads();
    {   // cross-mgrp reduction: thread -> one (channel, sample)
        int ch = tid >> 7, s = tid & 127;
        float sum = 0.f;
        #pragma unroll
        for (int mg = 0; mg < 16; mg++) sum += sRed[mg][ch][s];
        sum += b_sk2[ch];
        int n = n0 + s;
        if (ch == 0) outp[n] = sum;                       // means
        else         outp[NTOT + n] = __expf(0.5f*sum);   // stds
    }
}

// ---------------------------------------------------------------------------
extern "C" void kernel_launch(void* const* d_in, const int* in_sizes, int n_in,
                              void* d_out, int out_size)
{
    const float* x     = (const float*)d_in[0];
    const float* W_in  = (const float*)d_in[1];
    const float* b_in  = (const float*)d_in[2];
    const float* W_f   = (const float*)d_in[3];
    const float* b_f   = (const float*)d_in[4];
    const float* W_g   = (const float*)d_in[5];
    const float* b_g   = (const float*)d_in[6];
    const float* W_s   = (const float*)d_in[7];
    const float* b_s   = (const float*)d_in[8];
    const float* W_o   = (const float*)d_in[9];
    const float* b_o   = (const float*)d_in[10];
    const float* W_sk1 = (const float*)d_in[11];
    const float* b_sk1 = (const float*)d_in[12];
    const float* W_sk2 = (const float*)d_in[13];
    const float* b_sk2 = (const float*)d_in[14];
    float* outp = (float*)d_out;

    precompute_layer<<<NLAYER, 32>>>(W_in, b_in, W_f, b_f, W_g, b_g, W_o, b_o);
    precompute_skip<<<128, 256>>>(W_s, b_s, W_sk1, b_sk1);

    for (int i = 0; i < NLAYER; i++) {
        int d = 1 << (i & 7);
        layer_kernel<<<NTOT/(256*AU), 256>>>(x, i, d);
    }
    phaseB_kernel<<<NTOT/NT, 256>>>(W_sk2, b_sk2, outp);
}

// round 11
// speedup vs baseline: 2.7026x; 2.6939x over previous
#include <cuda_runtime.h>
#include <cuda_fp16.h>
#include <cstdint>

#define NLAYER 16
#define BATCH 8
#define TLEN 65536
#define NTOT (BATCH*TLEN)        // 524288
#define RES 32
#define KTOT (NLAYER*RES)        // 512

// per-layer coefficient layout (floats), stride 420
#define C_AF0 0
#define C_AF1 32
#define C_AF2 64
#define C_BFA 96
#define C_DF0 128
#define C_DF1 160
#define C_AG0 192
#define C_AG1 224
#define C_AG2 256
#define C_BGA 288
#define C_DG0 320
#define C_DG1 352
#define C_WO  384
#define C_BO  416
#define C_STRIDE 420

__device__ float  g_coef[NLAYER*C_STRIDE];
__device__ __half g_Gh[KTOT*64];     // folded (W_sk1 @ W_s_cat), fp16, layout [j][m]
__device__ float  g_C1[64];          // folded bias into pre-relu
__device__ float  g_bufA[NTOT];
__device__ float  g_bufB[NTOT];
__device__ __half g_gatedH[(size_t)KTOT*NTOT];   // 512 MiB scratch, layout [j][n]

// ---------------------------------------------------------------------------
// Precompute 1: collapse per-layer convs onto the scalar residual stream.
// ---------------------------------------------------------------------------
__global__ void precompute_layer(const float* __restrict__ W_in, const float* __restrict__ b_in,
                                 const float* __restrict__ W_f,  const float* __restrict__ b_f,
                                 const float* __restrict__ W_g,  const float* __restrict__ b_g,
                                 const float* __restrict__ W_o,  const float* __restrict__ b_o)
{
    int i = blockIdx.x;      // layer
    int c = threadIdx.x;     // out channel (32)
    float af[3] = {0,0,0}, df[3] = {0,0,0};
    float ag[3] = {0,0,0}, dg[3] = {0,0,0};
    for (int cin = 0; cin < 32; cin++) {
        float wi = W_in[i*32 + cin];
        float bi = b_in[i*32 + cin];
        #pragma unroll
        for (int k = 0; k < 3; k++) {
            float wf = W_f[((i*32 + c)*32 + cin)*3 + k];
            float wg = W_g[((i*32 + c)*32 + cin)*3 + k];
            af[k] = fmaf(wf, wi, af[k]);
            df[k] = fmaf(wf, bi, df[k]);
            ag[k] = fmaf(wg, wi, ag[k]);
            dg[k] = fmaf(wg, bi, dg[k]);
        }
    }
    float* cf = g_coef + i*C_STRIDE;
    cf[C_AF0+c] = af[0]; cf[C_AF1+c] = af[1]; cf[C_AF2+c] = af[2];
    cf[C_BFA+c] = b_f[i*32 + c] + df[0] + df[1] + df[2];
    cf[C_DF0+c] = df[0]; cf[C_DF1+c] = df[1];
    cf[C_AG0+c] = ag[0]; cf[C_AG1+c] = ag[1]; cf[C_AG2+c] = ag[2];
    cf[C_BGA+c] = b_g[i*32 + c] + dg[0] + dg[1] + dg[2];
    cf[C_DG0+c] = dg[0]; cf[C_DG1+c] = dg[1];
    cf[C_WO +c] = W_o[i*32 + c];
    if (c == 0) cf[C_BO] = b_o[i];
}

// ---------------------------------------------------------------------------
// Precompute 2: fold skip path to fp16 G and fp32 c1.
// ---------------------------------------------------------------------------
__global__ void precompute_skip(const float* __restrict__ W_s,   const float* __restrict__ b_s,
                                const float* __restrict__ W_sk1, const float* __restrict__ b_sk1)
{
    int gid = blockIdx.x*blockDim.x + threadIdx.x;
    if (gid < KTOT*64) {
        int j = gid >> 6, m = gid & 63;
        int i = j >> 5, c = j & 31;
        float acc = 0.f;
        for (int o = 0; o < 64; o++)
            acc = fmaf(W_sk1[m*64 + o], W_s[(i*64 + o)*32 + c], acc);
        g_Gh[j*64 + m] = __float2half_rn(acc);
    }
    if (gid < 64) {
        int m = gid;
        float acc = b_sk1[m];
        for (int o = 0; o < 64; o++) {
            float bs = 0.f;
            for (int i2 = 0; i2 < NLAYER; i2++) bs += b_s[i2*64 + o];
            acc = fmaf(W_sk1[m*64 + o], bs, acc);
        }
        g_C1[m] = acc;
    }
}

// ---------------------------------------------------------------------------
// Phase A: one kernel per layer on the collapsed rank-1 form.
// gated = tanh(pf)*sigmoid(pg) fused: (ef-1)*eg / ((ef+1)*(eg+1)), 3 MUFU.
// ---------------------------------------------------------------------------
#define AU 4
__global__ void __launch_bounds__(256) layer_kernel(const float* __restrict__ x, int layer, int d)
{
    __shared__ float cf[C_STRIDE];
    {
        const float* gc = g_coef + layer*C_STRIDE;
        for (int idx = threadIdx.x; idx < C_STRIDE; idx += 256) cf[idx] = gc[idx];
    }
    __syncthreads();

    const float* in = (layer == 0) ? x : ((layer & 1) ? g_bufA : g_bufB);
    float* out = (layer & 1) ? g_bufB : g_bufA;
    __half* gp = g_gatedH + (size_t)layer*RES*NTOT;

    int base = blockIdx.x*(256*AU) + threadIdx.x;

    float o0[AU], o1[AU], o2[AU], acc[AU];
    int tt[AU];
    #pragma unroll
    for (int u = 0; u < AU; u++) {
        int n = base + u*256;
        int t = n & (TLEN - 1);
        tt[u] = t;
        o2[u] = in[n];
        o1[u] = (t >= d)   ? in[n - d]   : 0.f;
        o0[u] = (t >= 2*d) ? in[n - 2*d] : 0.f;
        acc[u] = 0.f;
    }
    float bo = cf[C_BO];

    #pragma unroll 4
    for (int c = 0; c < RES; c++) {
        float af0 = cf[C_AF0+c], af1 = cf[C_AF1+c], af2 = cf[C_AF2+c], bfa = cf[C_BFA+c];
        float ag0 = cf[C_AG0+c], ag1 = cf[C_AG1+c], ag2 = cf[C_AG2+c], bga = cf[C_BGA+c];
        float wo  = cf[C_WO+c];
        __half* gout = gp + (size_t)c*NTOT;
        #pragma unroll
        for (int u = 0; u < AU; u++) {
            float pf = fmaf(af0, o0[u], fmaf(af1, o1[u], fmaf(af2, o2[u], bfa)));
            float pg = fmaf(ag0, o0[u], fmaf(ag1, o1[u], fmaf(ag2, o2[u], bga)));
            if (tt[u] < 2*d) {
                pf -= cf[C_DF0+c]; pg -= cf[C_DG0+c];
                if (tt[u] < d) { pf -= cf[C_DF1+c]; pg -= cf[C_DG1+c]; }
            }
            pf = fminf(fmaxf(pf, -15.f), 15.f);
            pg = fminf(fmaxf(pg, -30.f), 30.f);
            float ef = __expf(2.f*pf);
            float eg = __expf(pg);
            float gt = __fdividef((ef - 1.f)*eg, (ef + 1.f)*(eg + 1.f));
            gout[base + u*256] = __float2half_rn(gt);
            acc[u] = fmaf(wo, gt, acc[u]);
        }
    }
    #pragma unroll
    for (int u = 0; u < AU; u++) {
        int n = base + u*256;
        out[n] = o2[u] + acc[u] + bo;
    }
}

// ---------------------------------------------------------------------------
// Phase B: D[128 samples, 64 m] per block = X[samples,512] @ G[512,64],
// via HMMA m16n8k16 (fp16 in, fp32 acc), fused relu/head/exp epilogue.
// smem tiles are padded so ldmatrix row-stride ≡ 4 words (mod 32): conflict-free.
// ---------------------------------------------------------------------------
#define NT 128
#define KC 64
#define XPITCH 136   // halfs per row (272B; 68 words ≡ 4 mod 32)
#define GPITCH 72    // halfs per row (144B; 36 words ≡ 4 mod 32)

__device__ __forceinline__ uint32_t smem_u32(const void* p) {
    uint32_t a;
    asm("{ .reg .u64 t; cvta.to.shared.u64 t, %1; cvt.u32.u64 %0, t; }" : "=r"(a) : "l"(p));
    return a;
}

__global__ void __launch_bounds__(256) phaseB_kernel(const float* __restrict__ W_sk2,
                                                     const float* __restrict__ b_sk2,
                                                     float* __restrict__ outp)
{
    __shared__ __align__(16) __half sX[KC*XPITCH];   // 17408 B
    __shared__ __align__(16) __half sG[KC*GPITCH];   //  9216 B

    int tid  = threadIdx.x;
    int n0   = blockIdx.x * NT;
    int warp = tid >> 5, lane = tid & 31;
    int grp  = lane >> 2, tig = lane & 3;
    int s0   = warp * 16;              // this warp's 16 samples

    float c[8][4];
    #pragma unroll
    for (int a = 0; a < 8; a++)
        #pragma unroll
        for (int b = 0; b < 4; b++) c[a][b] = 0.f;

    // per-lane ldmatrix addresses
    int i8 = lane & 7, seg = lane >> 3;
    // A (samples x k) from sX[k][n]:  seg0:(k0+i, s0) seg1:(k0+i, s0+8) seg2:(k0+8+i, s0) seg3:(k0+8+i, s0+8)
    uint32_t aAddr = smem_u32(sX) +
        (uint32_t)(((i8 + (seg >> 1)*8)*XPITCH + s0 + (seg & 1)*8) * 2);
    // B (k x m) from sG[k][m]:       seg0:(k0+i, 0)  seg1:(k0+8+i, 0)  seg2:(k0+i, 8)  seg3:(k0+8+i, 8)
    uint32_t bAddr = smem_u32(sG) +
        (uint32_t)(((i8 + (seg & 1)*8)*GPITCH + (seg >> 1)*8) * 2);

    for (int jb = 0; jb < KTOT; jb += KC) {
        // stage X tile: 64 k-rows x 128 samples, coalesced float4
        #pragma unroll
        for (int it = 0; it < 4; it++) {
            int idx = it*256 + tid;
            int k = idx >> 4, noct = idx & 15;
            float4 v = *reinterpret_cast<const float4*>(
                &g_gatedH[(size_t)(jb + k)*NTOT + n0 + noct*8]);
            *reinterpret_cast<float4*>(&sX[k*XPITCH + noct*8]) = v;
        }
        // stage G tile: 64 k-rows x 64 m
        #pragma unroll
        for (int it = 0; it < 2; it++) {
            int idx = it*256 + tid;
            int k = idx >> 3, moct = idx & 7;
            float4 v = *reinterpret_cast<const float4*>(&g_Gh[(jb + k)*64 + moct*8]);
            *reinterpret_cast<float4*>(&sG[k*GPITCH + moct*8]) = v;
        }
        __syncthreads();

        #pragma unroll
        for (int ks = 0; ks < 4; ks++) {        // 4 k-steps of 16
            uint32_t a0, a1, a2, a3;
            asm volatile("ldmatrix.sync.aligned.m8n8.x4.trans.shared.b16 {%0,%1,%2,%3}, [%4];"
                         : "=r"(a0), "=r"(a1), "=r"(a2), "=r"(a3)
                         : "r"(aAddr + (uint32_t)(ks*16*XPITCH*2)));
            #pragma unroll
            for (int mp = 0; mp < 4; mp++) {    // m-pairs: tiles 2mp, 2mp+1
                uint32_t b0, b1, b2, b3;
                asm volatile("ldmatrix.sync.aligned.m8n8.x4.trans.shared.b16 {%0,%1,%2,%3}, [%4];"
                             : "=r"(b0), "=r"(b1), "=r"(b2), "=r"(b3)
                             : "r"(bAddr + (uint32_t)((ks*16*GPITCH + mp*16)*2)));
                asm volatile("mma.sync.aligned.m16n8k16.row.col.f32.f16.f16.f32 "
                             "{%0,%1,%2,%3}, {%4,%5,%6,%7}, {%8,%9}, {%0,%1,%2,%3};"
                             : "+f"(c[2*mp][0]), "+f"(c[2*mp][1]), "+f"(c[2*mp][2]), "+f"(c[2*mp][3])
                             : "r"(a0), "r"(a1), "r"(a2), "r"(a3), "r"(b0), "r"(b1));
                asm volatile("mma.sync.aligned.m16n8k16.row.col.f32.f16.f16.f32 "
                             "{%0,%1,%2,%3}, {%4,%5,%6,%7}, {%8,%9}, {%0,%1,%2,%3};"
                             : "+f"(c[2*mp+1][0]), "+f"(c[2*mp+1][1]), "+f"(c[2*mp+1][2]), "+f"(c[2*mp+1][3])
                             : "r"(a0), "r"(a1), "r"(a2), "r"(a3), "r"(b2), "r"(b3));
            }
        }
        __syncthreads();
    }

    // epilogue: +c1, relu, project to 2 channels, reduce across tig lanes
    float pa0 = 0.f, pa1 = 0.f, pb0 = 0.f, pb1 = 0.f;
    #pragma unroll
    for (int mt = 0; mt < 8; mt++) {
        int m = mt*8 + tig*2;
        float c1a = g_C1[m],     c1b = g_C1[m+1];
        float w0a = W_sk2[m],    w0b = W_sk2[m+1];
        float w1a = W_sk2[64+m], w1b = W_sk2[64+m+1];
        float v;
        v = fmaxf(c[mt][0] + c1a, 0.f); pa0 = fmaf(w0a, v, pa0); pa1 = fmaf(w1a, v, pa1);
        v = fmaxf(c[mt][1] + c1b, 0.f); pa0 = fmaf(w0b, v, pa0); pa1 = fmaf(w1b, v, pa1);
        v = fmaxf(c[mt][2] + c1a, 0.f); pb0 = fmaf(w0a, v, pb0); pb1 = fmaf(w1a, v, pb1);
        v = fmaxf(c[mt][3] + c1b, 0.f); pb0 = fmaf(w0b, v, pb0); pb1 = fmaf(w1b, v, pb1);
    }
    #pragma unroll
    for (int off = 1; off <= 2; off <<= 1) {
        pa0 += __shfl_xor_sync(0xFFFFFFFFu, pa0, off);
        pa1 += __shfl_xor_sync(0xFFFFFFFFu, pa1, off);
        pb0 += __shfl_xor_sync(0xFFFFFFFFu, pb0, off);
        pb1 += __shfl_xor_sync(0xFFFFFFFFu, pb1, off);
    }
    if (tig == 0) {
        int na = n0 + s0 + grp;
        int nb = na + 8;
        outp[na]        = pa0 + b_sk2[0];
        outp[NTOT + na] = __expf(0.5f*(pa1 + b_sk2[1]));
        outp[nb]        = pb0 + b_sk2[0];
        outp[NTOT + nb] = __expf(0.5f*(pb1 + b_sk2[1]));
    }
}

// ---------------------------------------------------------------------------
extern "C" void kernel_launch(void* const* d_in, const int* in_sizes, int n_in,
                              void* d_out, int out_size)
{
    const float* x     = (const float*)d_in[0];
    const float* W_in  = (const float*)d_in[1];
    const float* b_in  = (const float*)d_in[2];
    const float* W_f   = (const float*)d_in[3];
    const float* b_f   = (const float*)d_in[4];
    const float* W_g   = (const float*)d_in[5];
    const float* b_g   = (const float*)d_in[6];
    const float* W_s   = (const float*)d_in[7];
    const float* b_s   = (const float*)d_in[8];
    const float* W_o   = (const float*)d_in[9];
    const float* b_o   = (const float*)d_in[10];
    const float* W_sk1 = (const float*)d_in[11];
    const float* b_sk1 = (const float*)d_in[12];
    const float* W_sk2 = (const float*)d_in[13];
    const float* b_sk2 = (const float*)d_in[14];
    float* outp = (float*)d_out;

    precompute_layer<<<NLAYER, 32>>>(W_in, b_in, W_f, b_f, W_g, b_g, W_o, b_o);
    precompute_skip<<<128, 256>>>(W_s, b_s, W_sk1, b_sk1);

    for (int i = 0; i < NLAYER; i++) {
        int d = 1 << (i & 7);
        layer_kernel<<<NTOT/(256*AU), 256>>>(x, i, d);
    }
    phaseB_kernel<<<NTOT/NT, 256>>>(W_sk2, b_sk2, outp);
}